// round 12
// baseline (speedup 1.0000x reference)
#include <cuda_runtime.h>
#include <cuda_bf16.h>
#include <math.h>

#define BB 2
#define SS 2048
#define DD 1024
#define HH 16
#define HD 64
#define MROWS (BB*SS)          // 4096
#define QSCALE 0.1803368801111204f   // 0.125 * log2(e)

// ---------------- scratch (device globals; no allocation) ----------------
__device__ __align__(16) unsigned g_xn  [MROWS*DD/2];       // bf16 [M][D]
__device__ __align__(16) unsigned g_q   [BB*HH*SS*HD/2];    // bf16 [B,H,S,HD] (pre-scaled)
__device__ __align__(16) unsigned g_k   [BB*HH*SS*HD/2];
__device__ __align__(16) unsigned g_v   [BB*HH*SS*HD/2];
__device__ __align__(16) unsigned g_ctx [MROWS*DD/2];       // bf16 [B,S,D]
__device__ __align__(16) float    g_gt  [MROWS*DD];         // f32 gate pre-activation
__device__ __align__(16) unsigned g_wxT [4*DD*DD/2];        // bf16 [wq;wk;wv;wg]^T [4096][1024]
__device__ __align__(16) unsigned g_woT [DD*DD/2];          // bf16 [D][D]

// ---------------- helpers ----------------
__device__ __forceinline__ float ex2(float x) {
    float y; asm("ex2.approx.ftz.f32 %0, %1;" : "=f"(y) : "f"(x)); return y;
}
__device__ __forceinline__ unsigned pk(float lo, float hi) {
    unsigned r; asm("cvt.rn.bf16x2.f32 %0, %1, %2;" : "=r"(r) : "f"(hi), "f"(lo));
    return r;
}
__device__ __forceinline__ void mma16(float* d, const unsigned* a, const unsigned* b) {
    asm volatile(
        "mma.sync.aligned.m16n8k16.row.col.f32.bf16.bf16.f32 "
        "{%0,%1,%2,%3}, {%4,%5,%6,%7}, {%8,%9}, {%0,%1,%2,%3};"
        : "+f"(d[0]), "+f"(d[1]), "+f"(d[2]), "+f"(d[3])
        : "r"(a[0]), "r"(a[1]), "r"(a[2]), "r"(a[3]),
          "r"(b[0]), "r"(b[1]));
}
__device__ __forceinline__ void ldsm4(unsigned* r, const unsigned* p) {
    unsigned addr = (unsigned)__cvta_generic_to_shared(p);
    asm volatile("ldmatrix.sync.aligned.m8n8.x4.shared.b16 {%0,%1,%2,%3}, [%4];"
                 : "=r"(r[0]), "=r"(r[1]), "=r"(r[2]), "=r"(r[3]) : "r"(addr));
}
__device__ __forceinline__ void ldsm4t(unsigned* r, const unsigned* p) {
    unsigned addr = (unsigned)__cvta_generic_to_shared(p);
    asm volatile("ldmatrix.sync.aligned.m8n8.x4.trans.shared.b16 {%0,%1,%2,%3}, [%4];"
                 : "=r"(r[0]), "=r"(r[1]), "=r"(r[2]), "=r"(r[3]) : "r"(addr));
}
__device__ __forceinline__ void cpa(void* s, const void* g) {
    unsigned sa = (unsigned)__cvta_generic_to_shared(s);
    asm volatile("cp.async.cg.shared.global [%0], [%1], 16;" :: "r"(sa), "l"(g));
}
#define CP_COMMIT() asm volatile("cp.async.commit_group;" ::: "memory")
#define CP_WAIT(n)  asm volatile("cp.async.wait_group %0;" :: "n"(n) : "memory")

// ---------------- LayerNorm -> bf16 ----------------
__global__ __launch_bounds__(256) void ln_kernel(
    const float* __restrict__ x, const float* __restrict__ gamma,
    const float* __restrict__ beta)
{
    const int row = blockIdx.x;
    const int t = threadIdx.x;
    const float4 v = reinterpret_cast<const float4*>(x + (size_t)row * DD)[t];
    float s  = v.x + v.y + v.z + v.w;
    float s2 = v.x*v.x + v.y*v.y + v.z*v.z + v.w*v.w;
    #pragma unroll
    for (int o = 16; o > 0; o >>= 1) {
        s  += __shfl_xor_sync(0xFFFFFFFFu, s,  o);
        s2 += __shfl_xor_sync(0xFFFFFFFFu, s2, o);
    }
    __shared__ float ws[8], ws2[8];
    if ((t & 31) == 0) { ws[t >> 5] = s; ws2[t >> 5] = s2; }
    __syncthreads();
    float st = 0.f, st2 = 0.f;
    #pragma unroll
    for (int i = 0; i < 8; i++) { st += ws[i]; st2 += ws2[i]; }
    const float mu  = st * (1.f / DD);
    const float var = st2 * (1.f / DD) - mu * mu;
    const float inv = rsqrtf(var + 1e-5f);
    const float4 gm = reinterpret_cast<const float4*>(gamma)[t];
    const float4 bt = reinterpret_cast<const float4*>(beta)[t];
    uint2 o;
    o.x = pk((v.x - mu) * inv * gm.x + bt.x, (v.y - mu) * inv * gm.y + bt.y);
    o.y = pk((v.z - mu) * inv * gm.z + bt.z, (v.w - mu) * inv * gm.w + bt.w);
    reinterpret_cast<uint2*>(g_xn)[row * 256 + t] = o;
}

// ---------------- weight transpose + fp32->bf16 ----------------
__global__ __launch_bounds__(256) void wconv_a(
    const float* __restrict__ w_qkv, const float* __restrict__ w_gate)
{
    __shared__ float s[32][33];
    int bx = blockIdx.x;
    const float* src; int N; int rowoff;
    if (bx < 96) { src = w_qkv;  N = 3 * DD; rowoff = 0; }
    else         { src = w_gate; N = DD; bx -= 96; rowoff = 3 * DD; }
    __nv_bfloat16* dst = reinterpret_cast<__nv_bfloat16*>(g_wxT);
    const int tx = threadIdx.x, ty = threadIdx.y;
    const int n0 = bx << 5, k0 = blockIdx.y << 5;
    #pragma unroll
    for (int i = 0; i < 4; i++)
        s[ty + 8*i][tx] = src[(size_t)(k0 + ty + 8*i) * N + n0 + tx];
    __syncthreads();
    #pragma unroll
    for (int i = 0; i < 4; i++)
        dst[(size_t)(rowoff + n0 + ty + 8*i) * DD + k0 + tx] = __float2bfloat16(s[tx][ty + 8*i]);
}
__global__ __launch_bounds__(256) void wconv_b(const float* __restrict__ w_out)
{
    __shared__ float s[32][33];
    __nv_bfloat16* dst = reinterpret_cast<__nv_bfloat16*>(g_woT);
    const int tx = threadIdx.x, ty = threadIdx.y;
    const int n0 = blockIdx.x << 5, k0 = blockIdx.y << 5;
    #pragma unroll
    for (int i = 0; i < 4; i++)
        s[ty + 8*i][tx] = w_out[(size_t)(k0 + ty + 8*i) * DD + n0 + tx];
    __syncthreads();
    #pragma unroll
    for (int i = 0; i < 4; i++)
        dst[(size_t)(n0 + ty + 8*i) * DD + k0 + tx] = __float2bfloat16(s[tx][ty + 8*i]);
}

// ---------------- bf16 tensor GEMM: 128x64 CTA tile, 32x32 warp tiles,
// 8 warps, 4-stage cp.async, 3 CTAs/SM (occupancy experiment) ----------
//  mode 1: hybrid: cols <3072 -> scatter bf16 q/k/v (Q pre-scaled); cols >=3072 ->
//          gate pre-activation f32 (bias2) into C with row stride DD.
//  mode 3: fused out proj: C = (acc+bias)*sigmoid(fuse_g) + fuse_x, row stride DD.
#define NSTG 4
#define GSA 2560                    // A stage words: 128*20
#define GSB 1280                    // B stage words:  64*20
#define GEMM_SMEM_BYTES (NSTG * (GSA + GSB) * 4)   // 61440

__global__ __launch_bounds__(256, 3) void gemm_bf16(
    const __nv_bfloat16* __restrict__ A, const __nv_bfloat16* __restrict__ BT,
    const float* __restrict__ bias, const float* __restrict__ bias2,
    float* __restrict__ C,
    const float* __restrict__ fuse_g, const float* __restrict__ fuse_x,
    int K, int mode)
{
    extern __shared__ unsigned gsm[];
    unsigned* As = gsm;             // [NSTG][128][20]
    unsigned* Bs = gsm + NSTG * GSA;  // [NSTG][64][20]

    const int tid  = threadIdx.x;
    const int warp = tid >> 5, lane = tid & 31;
    const int wm = warp >> 1, wn = warp & 1;   // 4x2 warp grid, 32x32 tiles
    const int g  = lane >> 2, tg = lane & 3;
    const int lm = lane >> 3, lr = lane & 7;
    const int brow = blockIdx.y << 7, bcol = blockIdx.x << 6;

    float acc[2][4][4];
    #pragma unroll
    for (int i = 0; i < 2; i++)
        #pragma unroll
        for (int j = 0; j < 4; j++)
            #pragma unroll
            for (int k = 0; k < 4; k++) acc[i][j][k] = 0.f;

    const int arow = tid >> 1;            // A tile row (0..127)
    const int akp  = (tid & 1) << 3;      // A word offset 0 / 8
    const int brw  = tid >> 2;            // B tile row (0..63)
    const int bwo  = (tid & 3) << 2;      // B word offset 0/4/8/12

    auto issue = [&](int kt) {
        const int sta = (kt % NSTG) * GSA + arow * 20 + akp;
        const int stb = (kt % NSTG) * GSB + brw * 20 + bwo;
        const char* ga = (const char*)(A  + (size_t)(brow + arow) * K + kt * 32 + akp * 2);
        const char* gb = (const char*)(BT + (size_t)(bcol + brw)  * K + kt * 32 + bwo * 2);
        cpa(&As[sta],     ga);
        cpa(&As[sta + 4], ga + 16);
        cpa(&Bs[stb],     gb);
    };
    auto compute = [&](int buf) {
        const unsigned* Ab = As + buf * GSA;
        const unsigned* Bb = Bs + buf * GSB;
        #pragma unroll
        for (int step = 0; step < 2; step++) {
            const int lcol = (step << 3) + ((lm >> 1) << 2);
            unsigned af[2][4];
            #pragma unroll
            for (int mt = 0; mt < 2; mt++) {
                const int row = (wm << 5) + (mt << 4) + ((lm & 1) << 3) + lr;
                ldsm4(af[mt], &Ab[row * 20 + lcol]);
            }
            unsigned bfg[4][2];
            #pragma unroll
            for (int np = 0; np < 2; np++) {
                const int row = (wn << 5) + (np << 4) + ((lm & 1) << 3) + lr;
                unsigned t[4];
                ldsm4(t, &Bb[row * 20 + lcol]);
                bfg[np*2][0]   = t[0]; bfg[np*2+1][0] = t[1];
                bfg[np*2][1]   = t[2]; bfg[np*2+1][1] = t[3];
            }
            #pragma unroll
            for (int mt = 0; mt < 2; mt++)
                #pragma unroll
                for (int nt = 0; nt < 4; nt++)
                    mma16(acc[mt][nt], af[mt], bfg[nt]);
        }
    };

    const int nk = K >> 5;
    issue(0); CP_COMMIT();
    issue(1); CP_COMMIT();
    issue(2); CP_COMMIT();
    for (int kt = 0; kt < nk; kt++) {
        CP_WAIT(2);
        __syncthreads();                   // stage kt ready; prior compute fenced
        if (kt + 3 < nk) issue(kt + 3);
        CP_COMMIT();                       // always commit: keeps group count exact
        compute(kt % NSTG);
    }

    // epilogue
    #pragma unroll
    for (int mt = 0; mt < 2; mt++) {
        #pragma unroll
        for (int nt = 0; nt < 4; nt++) {
            const int r0 = brow + (wm << 5) + (mt << 4) + g;
            const int c0 = bcol + (wn << 5) + (nt << 3) + (tg << 1);
            float b0, b1;
            if (mode == 1 && c0 >= 3 * DD) {
                b0 = bias2[c0 - 3 * DD]; b1 = bias2[c0 - 3 * DD + 1];
            } else {
                b0 = bias[c0]; b1 = bias[c0 + 1];
            }
            float v00 = acc[mt][nt][0] + b0, v01 = acc[mt][nt][1] + b1;
            float v10 = acc[mt][nt][2] + b0, v11 = acc[mt][nt][3] + b1;
            if (mode == 1) {
                if (c0 < 3 * DD) {
                    const int which = c0 >> 10;
                    const int h = (c0 >> 6) & 15;
                    const int d = c0 & 63;
                    unsigned* dst = (which == 0) ? g_q : (which == 1) ? g_k : g_v;
                    if (which == 0) {   // fold softmax scale (base-2) into Q
                        v00 *= QSCALE; v01 *= QSCALE; v10 *= QSCALE; v11 *= QSCALE;
                    }
                    #pragma unroll
                    for (int rr = 0; rr < 2; rr++) {
                        const int r = r0 + rr * 8;
                        const int b = r >> 11, s = r & 2047;
                        const size_t idx = (((size_t)((b * HH + h) * SS + s)) * HD + d) >> 1;
                        dst[idx] = rr ? pk(v10, v11) : pk(v00, v01);
                    }
                } else {
                    const int cg = c0 - 3 * DD;
                    *reinterpret_cast<float2*>(&C[(size_t)r0 * DD + cg])       = make_float2(v00, v01);
                    *reinterpret_cast<float2*>(&C[(size_t)(r0 + 8) * DD + cg]) = make_float2(v10, v11);
                }
            } else {   // mode 3: fused (acc+bias)*sigmoid(g) + x
                #pragma unroll
                for (int rr = 0; rr < 2; rr++) {
                    const int r = r0 + rr * 8;
                    const float va = rr ? v10 : v00, vb = rr ? v11 : v01;
                    const size_t off = (size_t)r * DD + c0;
                    const float2 gv = *reinterpret_cast<const float2*>(&fuse_g[off]);
                    const float2 xv = *reinterpret_cast<const float2*>(&fuse_x[off]);
                    float2 res;
                    res.x = va / (1.f + ex2(-gv.x * 1.44269504f)) + xv.x;
                    res.y = vb / (1.f + ex2(-gv.y * 1.44269504f)) + xv.y;
                    *reinterpret_cast<float2*>(&C[off]) = res;
                }
            }
        }
    }
}

// ---------------- flash attention: 3-stage 64-key K/V ring, base-2 softmax ------
#define NT (SS / 64)
#define ATST (64 * 36)                       // words per operand per stage
#define ATT_SMEM_BYTES (6 * ATST * 4)        // 3 stages x (K+V) = 55296 B

__global__ __launch_bounds__(256) void attn_kernel()
{
    extern __shared__ unsigned asmem[];
    unsigned* Ksb = asmem;                   // [3][64][36]
    unsigned* Vsb = asmem + 3 * ATST;        // [3][64][36]

    const int tid  = threadIdx.x;
    const int warp = tid >> 5, lane = tid & 31;
    const int g  = lane >> 2, tg = lane & 3;
    const int lm = lane >> 3, lr = lane & 7;
    const int bh = blockIdx.y;
    const int q0 = blockIdx.x << 7;
    const int mr0 = warp << 4;

    const unsigned* Qg = g_q + (size_t)bh * SS * 32;
    const unsigned* Kg = g_k + (size_t)bh * SS * 32;
    const unsigned* Vg = g_v + (size_t)bh * SS * 32;

    unsigned qf[4][4];
    {
        const unsigned* r0p = Qg + (size_t)(q0 + mr0 + g) * 32;
        const unsigned* r1p = Qg + (size_t)(q0 + mr0 + g + 8) * 32;
        #pragma unroll
        for (int kc = 0; kc < 4; kc++) {
            qf[kc][0] = r0p[kc*8 + tg];
            qf[kc][1] = r1p[kc*8 + tg];
            qf[kc][2] = r0p[kc*8 + tg + 4];
            qf[kc][3] = r1p[kc*8 + tg + 4];
        }
    }

    float m0 = -1e30f, m1 = -1e30f, l0 = 0.f, l1 = 0.f;
    float oacc[8][4];
    #pragma unroll
    for (int j = 0; j < 8; j++)
        #pragma unroll
        for (int k = 0; k < 4; k++) oacc[j][k] = 0.f;

    const int ld_row = tid >> 2, ld_wo = (tid & 3) << 3;

    auto load = [&](int kt) {
        const int stg = (kt % 3) * ATST + ld_row * 36 + ld_wo;
        const char* gk = (const char*)(Kg + (size_t)(kt * 64 + ld_row) * 32 + ld_wo);
        const char* gv = (const char*)(Vg + (size_t)(kt * 64 + ld_row) * 32 + ld_wo);
        cpa(&Ksb[stg],     gk);
        cpa(&Ksb[stg + 4], gk + 16);
        cpa(&Vsb[stg],     gv);
        cpa(&Vsb[stg + 4], gv + 16);
    };

    load(0); CP_COMMIT();
    load(1); CP_COMMIT();
    for (int kt = 0; kt < NT; kt++) {
        const unsigned* Kh = Ksb + (kt % 3) * ATST;
        const unsigned* Vh = Vsb + (kt % 3) * ATST;
        CP_WAIT(1);
        __syncthreads();                     // tile kt ready; prior compute fenced
        if (kt + 2 < NT) load(kt + 2);       // overwrites stage (kt-1)%3: safe post-sync
        CP_COMMIT();                         // always commit: keeps group count exact

        float sacc[8][4];
        #pragma unroll
        for (int j = 0; j < 8; j++)
            #pragma unroll
            for (int k = 0; k < 4; k++) sacc[j][k] = 0.f;

        #pragma unroll
        for (int kc = 0; kc < 4; kc++) {
            const int lcol = kc*8 + ((lm >> 1) << 2);
            #pragma unroll
            for (int np = 0; np < 4; np++) {
                unsigned t[4];
                ldsm4(t, &Kh[(np*16 + ((lm & 1) << 3) + lr) * 36 + lcol]);
                unsigned b0[2] = { t[0], t[2] };
                unsigned b1[2] = { t[1], t[3] };
                mma16(sacc[np*2],     qf[kc], b0);
                mma16(sacc[np*2 + 1], qf[kc], b1);
            }
        }

        float mx0 = sacc[0][0], mx1 = sacc[0][2];
        #pragma unroll
        for (int nt = 0; nt < 8; nt++) {
            mx0 = fmaxf(mx0, fmaxf(sacc[nt][0], sacc[nt][1]));
            mx1 = fmaxf(mx1, fmaxf(sacc[nt][2], sacc[nt][3]));
        }
        mx0 = fmaxf(mx0, __shfl_xor_sync(0xFFFFFFFFu, mx0, 1));
        mx0 = fmaxf(mx0, __shfl_xor_sync(0xFFFFFFFFu, mx0, 2));
        mx1 = fmaxf(mx1, __shfl_xor_sync(0xFFFFFFFFu, mx1, 1));
        mx1 = fmaxf(mx1, __shfl_xor_sync(0xFFFFFFFFu, mx1, 2));
        const float M0 = fmaxf(m0, mx0), M1 = fmaxf(m1, mx1);
        const float f0 = ex2(m0 - M0), f1 = ex2(m1 - M1);
        m0 = M0; m1 = M1;

        float sum0 = 0.f, sum1 = 0.f;
        #pragma unroll
        for (int nt = 0; nt < 8; nt++) {
            const float p0 = ex2(sacc[nt][0] - M0);
            const float p1 = ex2(sacc[nt][1] - M0);
            const float p2 = ex2(sacc[nt][2] - M1);
            const float p3 = ex2(sacc[nt][3] - M1);
            sacc[nt][0] = p0; sacc[nt][1] = p1; sacc[nt][2] = p2; sacc[nt][3] = p3;
            sum0 += p0 + p1; sum1 += p2 + p3;
        }
        sum0 += __shfl_xor_sync(0xFFFFFFFFu, sum0, 1);
        sum0 += __shfl_xor_sync(0xFFFFFFFFu, sum0, 2);
        sum1 += __shfl_xor_sync(0xFFFFFFFFu, sum1, 1);
        sum1 += __shfl_xor_sync(0xFFFFFFFFu, sum1, 2);
        l0 = l0 * f0 + sum0;
        l1 = l1 * f1 + sum1;

        #pragma unroll
        for (int nt = 0; nt < 8; nt++) {
            oacc[nt][0] *= f0; oacc[nt][1] *= f0;
            oacc[nt][2] *= f1; oacc[nt][3] *= f1;
        }

        unsigned pf[4][4];
        #pragma unroll
        for (int kc = 0; kc < 4; kc++) {
            pf[kc][0] = pk(sacc[2*kc][0],     sacc[2*kc][1]);
            pf[kc][1] = pk(sacc[2*kc][2],     sacc[2*kc][3]);
            pf[kc][2] = pk(sacc[2*kc + 1][0], sacc[2*kc + 1][1]);
            pf[kc][3] = pk(sacc[2*kc + 1][2], sacc[2*kc + 1][3]);
        }

        #pragma unroll
        for (int kc = 0; kc < 4; kc++) {
            const int vrow = kc*16 + ((lm & 1) << 3) + lr;
            #pragma unroll
            for (int np2 = 0; np2 < 4; np2++) {
                const int vcol = np2*8 + ((lm >> 1) << 2);
                unsigned t[4];
                ldsm4t(t, &Vh[vrow * 36 + vcol]);
                unsigned b0[2] = { t[0], t[1] };
                unsigned b1[2] = { t[2], t[3] };
                mma16(oacc[np2*2],     pf[kc], b0);
                mma16(oacc[np2*2 + 1], pf[kc], b1);
            }
        }
    }

    const int b = bh >> 4, h = bh & 15;
    const float inv0 = 1.f / l0, inv1 = 1.f / l1;
    const size_t row0 = (size_t)(b * SS + q0 + mr0 + g)     * (DD/2) + h * (HD/2);
    const size_t row1 = (size_t)(b * SS + q0 + mr0 + g + 8) * (DD/2) + h * (HD/2);
    #pragma unroll
    for (int nt = 0; nt < 8; nt++) {
        g_ctx[row0 + nt*4 + tg] = pk(oacc[nt][0] * inv0, oacc[nt][1] * inv0);
        g_ctx[row1 + nt*4 + tg] = pk(oacc[nt][2] * inv1, oacc[nt][3] * inv1);
    }
}

// ---------------- launch ----------------
extern "C" void kernel_launch(void* const* d_in, const int* in_sizes, int n_in,
                              void* d_out, int out_size)
{
    const float* x      = (const float*)d_in[0];
    const float* gamma  = (const float*)d_in[1];
    const float* beta   = (const float*)d_in[2];
    const float* w_qkv  = (const float*)d_in[3];
    const float* b_qkv  = (const float*)d_in[4];
    const float* w_out  = (const float*)d_in[5];
    const float* b_out  = (const float*)d_in[6];
    const float* w_gate = (const float*)d_in[7];
    const float* b_gate = (const float*)d_in[8];
    float* out = (float*)d_out;

    void *p_xn, *p_ctx, *p_gt, *p_wx, *p_wo;
    cudaGetSymbolAddress(&p_xn,  g_xn);
    cudaGetSymbolAddress(&p_ctx, g_ctx);
    cudaGetSymbolAddress(&p_gt,  g_gt);
    cudaGetSymbolAddress(&p_wx,  g_wxT);
    cudaGetSymbolAddress(&p_wo,  g_woT);

    cudaFuncSetAttribute(gemm_bf16,
                         cudaFuncAttributeMaxDynamicSharedMemorySize,
                         GEMM_SMEM_BYTES);
    cudaFuncSetAttribute(attn_kernel,
                         cudaFuncAttributeMaxDynamicSharedMemorySize,
                         ATT_SMEM_BYTES);

    ln_kernel<<<MROWS, 256>>>(x, gamma, beta);

    wconv_a<<<dim3(128, 32), dim3(32, 8)>>>(w_qkv, w_gate);
    wconv_b<<<dim3(32, 32),  dim3(32, 8)>>>(w_out);

    // merged QKV+gate: [4096,1024] x [4096,1024]^T, 128x64 tiles
    gemm_bf16<<<dim3(64, 32), 256, GEMM_SMEM_BYTES>>>(
        (const __nv_bfloat16*)p_xn, (const __nv_bfloat16*)p_wx,
        b_qkv, b_gate, (float*)p_gt, nullptr, nullptr, DD, 1);

    attn_kernel<<<dim3(SS / 128, BB * HH), 256, ATT_SMEM_BYTES>>>();

    // out proj fused: (ctx@w_out + b_out) * sigmoid(g_gt) + x -> d_out
    gemm_bf16<<<dim3(16, 32), 256, GEMM_SMEM_BYTES>>>(
        (const __nv_bfloat16*)p_ctx, (const __nv_bfloat16*)p_wo,
        b_out, nullptr, out, (const float*)p_gt, x, DD, 3);
}

// round 13
// speedup vs baseline: 1.0367x; 1.0367x over previous
#include <cuda_runtime.h>
#include <cuda_bf16.h>
#include <math.h>

#define BB 2
#define SS 2048
#define DD 1024
#define HH 16
#define HD 64
#define MROWS (BB*SS)          // 4096
#define QSCALE 0.1803368801111204f   // 0.125 * log2(e)

// ---------------- scratch (device globals; no allocation) ----------------
__device__ __align__(16) unsigned g_xn  [MROWS*DD/2];       // bf16 [M][D]
__device__ __align__(16) unsigned g_q   [BB*HH*SS*HD/2];    // bf16 [B,H,S,HD] (pre-scaled)
__device__ __align__(16) unsigned g_k   [BB*HH*SS*HD/2];
__device__ __align__(16) unsigned g_v   [BB*HH*SS*HD/2];
__device__ __align__(16) unsigned g_ctx [MROWS*DD/2];       // bf16 [B,S,D]
__device__ __align__(16) float    g_gt  [MROWS*DD];         // f32 gate pre-activation
__device__ __align__(16) unsigned g_wxT [4*DD*DD/2];        // bf16 [wq;wk;wv;wg]^T [4096][1024]
__device__ __align__(16) unsigned g_woT [DD*DD/2];          // bf16 [D][D]

// ---------------- helpers ----------------
__device__ __forceinline__ float ex2(float x) {
    float y; asm("ex2.approx.ftz.f32 %0, %1;" : "=f"(y) : "f"(x)); return y;
}
__device__ __forceinline__ unsigned pk(float lo, float hi) {
    unsigned r; asm("cvt.rn.bf16x2.f32 %0, %1, %2;" : "=r"(r) : "f"(hi), "f"(lo));
    return r;
}
__device__ __forceinline__ void mma16(float* d, const unsigned* a, const unsigned* b) {
    asm volatile(
        "mma.sync.aligned.m16n8k16.row.col.f32.bf16.bf16.f32 "
        "{%0,%1,%2,%3}, {%4,%5,%6,%7}, {%8,%9}, {%0,%1,%2,%3};"
        : "+f"(d[0]), "+f"(d[1]), "+f"(d[2]), "+f"(d[3])
        : "r"(a[0]), "r"(a[1]), "r"(a[2]), "r"(a[3]),
          "r"(b[0]), "r"(b[1]));
}
__device__ __forceinline__ void ldsm4(unsigned* r, const unsigned* p) {
    unsigned addr = (unsigned)__cvta_generic_to_shared(p);
    asm volatile("ldmatrix.sync.aligned.m8n8.x4.shared.b16 {%0,%1,%2,%3}, [%4];"
                 : "=r"(r[0]), "=r"(r[1]), "=r"(r[2]), "=r"(r[3]) : "r"(addr));
}
__device__ __forceinline__ void ldsm4t(unsigned* r, const unsigned* p) {
    unsigned addr = (unsigned)__cvta_generic_to_shared(p);
    asm volatile("ldmatrix.sync.aligned.m8n8.x4.trans.shared.b16 {%0,%1,%2,%3}, [%4];"
                 : "=r"(r[0]), "=r"(r[1]), "=r"(r[2]), "=r"(r[3]) : "r"(addr));
}
__device__ __forceinline__ void cpa(void* s, const void* g) {
    unsigned sa = (unsigned)__cvta_generic_to_shared(s);
    asm volatile("cp.async.cg.shared.global [%0], [%1], 16;" :: "r"(sa), "l"(g));
}
#define CP_COMMIT() asm volatile("cp.async.commit_group;" ::: "memory")
#define CP_WAIT(n)  asm volatile("cp.async.wait_group %0;" :: "n"(n) : "memory")

// ---------------- fused prologue: LayerNorm + all weight transposes ----------
// blocks [0, MROWS)               : LayerNorm row -> g_xn (bf16)
// blocks [MROWS, MROWS+4096)      : wconv for w_qkv/w_gate -> g_wxT
// blocks [MROWS+4096, MROWS+5120) : wconv for w_out -> g_woT
__global__ __launch_bounds__(256) void prologue(
    const float* __restrict__ x, const float* __restrict__ gamma,
    const float* __restrict__ beta,
    const float* __restrict__ w_qkv, const float* __restrict__ w_gate,
    const float* __restrict__ w_out)
{
    int blk = blockIdx.x;
    const int tid = threadIdx.x;

    if (blk < MROWS) {
        // ---- LayerNorm ----
        const int row = blk;
        const float4 v = reinterpret_cast<const float4*>(x + (size_t)row * DD)[tid];
        float s  = v.x + v.y + v.z + v.w;
        float s2 = v.x*v.x + v.y*v.y + v.z*v.z + v.w*v.w;
        #pragma unroll
        for (int o = 16; o > 0; o >>= 1) {
            s  += __shfl_xor_sync(0xFFFFFFFFu, s,  o);
            s2 += __shfl_xor_sync(0xFFFFFFFFu, s2, o);
        }
        __shared__ float ws[8], ws2[8];
        if ((tid & 31) == 0) { ws[tid >> 5] = s; ws2[tid >> 5] = s2; }
        __syncthreads();
        float st = 0.f, st2 = 0.f;
        #pragma unroll
        for (int i = 0; i < 8; i++) { st += ws[i]; st2 += ws2[i]; }
        const float mu  = st * (1.f / DD);
        const float var = st2 * (1.f / DD) - mu * mu;
        const float inv = rsqrtf(var + 1e-5f);
        const float4 gm = reinterpret_cast<const float4*>(gamma)[tid];
        const float4 bt = reinterpret_cast<const float4*>(beta)[tid];
        uint2 o;
        o.x = pk((v.x - mu) * inv * gm.x + bt.x, (v.y - mu) * inv * gm.y + bt.y);
        o.y = pk((v.z - mu) * inv * gm.z + bt.z, (v.w - mu) * inv * gm.w + bt.w);
        reinterpret_cast<uint2*>(g_xn)[row * 256 + tid] = o;
        return;
    }

    // ---- weight transpose + fp32->bf16 ----
    blk -= MROWS;
    __shared__ float s[32][33];
    const int tx = tid & 31, ty = tid >> 5;
    const float* src; unsigned* dstw; int N, rowoff, bx, by;
    if (blk < 4096) {                    // w_qkv / w_gate -> g_wxT
        bx = blk & 127; by = blk >> 7;
        if (bx < 96) { src = w_qkv;  N = 3 * DD; rowoff = 0; }
        else         { src = w_gate; N = DD; bx -= 96; rowoff = 3 * DD; }
        dstw = g_wxT;
    } else {                             // w_out -> g_woT
        blk -= 4096;
        bx = blk & 31; by = blk >> 5;
        src = w_out; N = DD; rowoff = 0; dstw = g_woT;
    }
    __nv_bfloat16* dst = reinterpret_cast<__nv_bfloat16*>(dstw);
    const int n0 = bx << 5, k0 = by << 5;
    #pragma unroll
    for (int i = 0; i < 4; i++)
        s[ty + 8*i][tx] = src[(size_t)(k0 + ty + 8*i) * N + n0 + tx];
    __syncthreads();
    #pragma unroll
    for (int i = 0; i < 4; i++)
        dst[(size_t)(rowoff + n0 + ty + 8*i) * DD + k0 + tx] = __float2bfloat16(s[tx][ty + 8*i]);
}

// ---------------- bf16 tensor GEMM (round-11 proven config, 5 stages) ----------
// 8 warps, 128x128 CTA tile, 32x64 warp tiles, cp.async 5-stage.
//  mode 1: hybrid: cols <3072 -> scatter bf16 q/k/v (Q pre-scaled); cols >=3072 ->
//          gate pre-activation f32 (bias2) into C with row stride DD.
//  mode 3: fused out proj: C = (acc+bias)*sigmoid(fuse_g) + fuse_x, row stride DD.
#define NSTG 5
#define GS 2560                     // words per stage per operand: 128*20
#define GEMM_SMEM_BYTES (2 * NSTG * GS * 4)   // 102400

__global__ __launch_bounds__(256, 2) void gemm_bf16(
    const __nv_bfloat16* __restrict__ A, const __nv_bfloat16* __restrict__ BT,
    const float* __restrict__ bias, const float* __restrict__ bias2,
    float* __restrict__ C,
    const float* __restrict__ fuse_g, const float* __restrict__ fuse_x,
    int K, int mode)
{
    extern __shared__ unsigned gsm[];
    unsigned* As = gsm;             // [NSTG][128][20]
    unsigned* Bs = gsm + NSTG * GS;

    const int tid  = threadIdx.x;
    const int warp = tid >> 5, lane = tid & 31;
    const int wm = warp >> 1, wn = warp & 1;
    const int g  = lane >> 2, tg = lane & 3;
    const int lm = lane >> 3, lr = lane & 7;
    const int brow = blockIdx.y << 7, bcol = blockIdx.x << 7;

    float acc[2][8][4];
    #pragma unroll
    for (int i = 0; i < 2; i++)
        #pragma unroll
        for (int j = 0; j < 8; j++)
            #pragma unroll
            for (int k = 0; k < 4; k++) acc[i][j][k] = 0.f;

    const int arow = tid >> 1;            // tile row (A and BT)
    const int akp  = (tid & 1) << 3;      // word offset 0 / 8

    auto issue = [&](int kt) {
        const int st = (kt % NSTG) * GS + arow * 20 + akp;
        const char* ga = (const char*)(A  + (size_t)(brow + arow) * K + kt * 32 + akp * 2);
        const char* gb = (const char*)(BT + (size_t)(bcol + arow) * K + kt * 32 + akp * 2);
        cpa(&As[st],     ga);
        cpa(&As[st + 4], ga + 16);
        cpa(&Bs[st],     gb);
        cpa(&Bs[st + 4], gb + 16);
    };
    auto compute = [&](int buf) {
        const unsigned* Ab = As + buf * GS;
        const unsigned* Bb = Bs + buf * GS;
        #pragma unroll
        for (int step = 0; step < 2; step++) {
            const int lcol = (step << 3) + ((lm >> 1) << 2);
            unsigned af[2][4];
            #pragma unroll
            for (int mt = 0; mt < 2; mt++) {
                const int row = (wm << 5) + (mt << 4) + ((lm & 1) << 3) + lr;
                ldsm4(af[mt], &Ab[row * 20 + lcol]);
            }
            unsigned bfg[8][2];
            #pragma unroll
            for (int np = 0; np < 4; np++) {
                const int row = (wn << 6) + (np << 4) + ((lm & 1) << 3) + lr;
                unsigned t[4];
                ldsm4(t, &Bb[row * 20 + lcol]);
                bfg[np*2][0]   = t[0]; bfg[np*2+1][0] = t[1];
                bfg[np*2][1]   = t[2]; bfg[np*2+1][1] = t[3];
            }
            #pragma unroll
            for (int mt = 0; mt < 2; mt++)
                #pragma unroll
                for (int nt = 0; nt < 8; nt++)
                    mma16(acc[mt][nt], af[mt], bfg[nt]);
        }
    };

    const int nk = K >> 5;
    issue(0); CP_COMMIT();
    issue(1); CP_COMMIT();
    issue(2); CP_COMMIT();
    issue(3); CP_COMMIT();
    for (int kt = 0; kt < nk; kt++) {
        CP_WAIT(3);
        __syncthreads();                   // stage kt ready; prior compute fenced
        if (kt + 4 < nk) issue(kt + 4);    // overwrites stage (kt-1)%5: safe post-sync
        CP_COMMIT();                       // always commit: keeps group count exact
        compute(kt % NSTG);
    }

    // epilogue
    #pragma unroll
    for (int mt = 0; mt < 2; mt++) {
        #pragma unroll
        for (int nt = 0; nt < 8; nt++) {
            const int r0 = brow + (wm << 5) + (mt << 4) + g;
            const int c0 = bcol + (wn << 6) + (nt << 3) + (tg << 1);
            float b0, b1;
            if (mode == 1 && c0 >= 3 * DD) {
                b0 = bias2[c0 - 3 * DD]; b1 = bias2[c0 - 3 * DD + 1];
            } else {
                b0 = bias[c0]; b1 = bias[c0 + 1];
            }
            float v00 = acc[mt][nt][0] + b0, v01 = acc[mt][nt][1] + b1;
            float v10 = acc[mt][nt][2] + b0, v11 = acc[mt][nt][3] + b1;
            if (mode == 1) {
                if (c0 < 3 * DD) {
                    const int which = c0 >> 10;
                    const int h = (c0 >> 6) & 15;
                    const int d = c0 & 63;
                    unsigned* dst = (which == 0) ? g_q : (which == 1) ? g_k : g_v;
                    if (which == 0) {   // fold softmax scale (base-2) into Q
                        v00 *= QSCALE; v01 *= QSCALE; v10 *= QSCALE; v11 *= QSCALE;
                    }
                    #pragma unroll
                    for (int rr = 0; rr < 2; rr++) {
                        const int r = r0 + rr * 8;
                        const int b = r >> 11, s = r & 2047;
                        const size_t idx = (((size_t)((b * HH + h) * SS + s)) * HD + d) >> 1;
                        dst[idx] = rr ? pk(v10, v11) : pk(v00, v01);
                    }
                } else {
                    const int cg = c0 - 3 * DD;
                    *reinterpret_cast<float2*>(&C[(size_t)r0 * DD + cg])       = make_float2(v00, v01);
                    *reinterpret_cast<float2*>(&C[(size_t)(r0 + 8) * DD + cg]) = make_float2(v10, v11);
                }
            } else {   // mode 3: fused (acc+bias)*sigmoid(g) + x
                #pragma unroll
                for (int rr = 0; rr < 2; rr++) {
                    const int r = r0 + rr * 8;
                    const float va = rr ? v10 : v00, vb = rr ? v11 : v01;
                    const size_t off = (size_t)r * DD + c0;
                    const float2 gv = *reinterpret_cast<const float2*>(&fuse_g[off]);
                    const float2 xv = *reinterpret_cast<const float2*>(&fuse_x[off]);
                    float2 res;
                    res.x = va / (1.f + ex2(-gv.x * 1.44269504f)) + xv.x;
                    res.y = vb / (1.f + ex2(-gv.y * 1.44269504f)) + xv.y;
                    *reinterpret_cast<float2*>(&C[off]) = res;
                }
            }
        }
    }
}

// ---------------- flash attention: 3-stage 64-key K/V ring, base-2 softmax ------
#define NT (SS / 64)
#define ATST (64 * 36)                       // words per operand per stage
#define ATT_SMEM_BYTES (6 * ATST * 4)        // 3 stages x (K+V) = 55296 B

__global__ __launch_bounds__(256) void attn_kernel()
{
    extern __shared__ unsigned asmem[];
    unsigned* Ksb = asmem;                   // [3][64][36]
    unsigned* Vsb = asmem + 3 * ATST;        // [3][64][36]

    const int tid  = threadIdx.x;
    const int warp = tid >> 5, lane = tid & 31;
    const int g  = lane >> 2, tg = lane & 3;
    const int lm = lane >> 3, lr = lane & 7;
    const int bh = blockIdx.y;
    const int q0 = blockIdx.x << 7;
    const int mr0 = warp << 4;

    const unsigned* Qg = g_q + (size_t)bh * SS * 32;
    const unsigned* Kg = g_k + (size_t)bh * SS * 32;
    const unsigned* Vg = g_v + (size_t)bh * SS * 32;

    unsigned qf[4][4];
    {
        const unsigned* r0p = Qg + (size_t)(q0 + mr0 + g) * 32;
        const unsigned* r1p = Qg + (size_t)(q0 + mr0 + g + 8) * 32;
        #pragma unroll
        for (int kc = 0; kc < 4; kc++) {
            qf[kc][0] = r0p[kc*8 + tg];
            qf[kc][1] = r1p[kc*8 + tg];
            qf[kc][2] = r0p[kc*8 + tg + 4];
            qf[kc][3] = r1p[kc*8 + tg + 4];
        }
    }

    float m0 = -1e30f, m1 = -1e30f, l0 = 0.f, l1 = 0.f;
    float oacc[8][4];
    #pragma unroll
    for (int j = 0; j < 8; j++)
        #pragma unroll
        for (int k = 0; k < 4; k++) oacc[j][k] = 0.f;

    const int ld_row = tid >> 2, ld_wo = (tid & 3) << 3;

    auto load = [&](int kt) {
        const int stg = (kt % 3) * ATST + ld_row * 36 + ld_wo;
        const char* gk = (const char*)(Kg + (size_t)(kt * 64 + ld_row) * 32 + ld_wo);
        const char* gv = (const char*)(Vg + (size_t)(kt * 64 + ld_row) * 32 + ld_wo);
        cpa(&Ksb[stg],     gk);
        cpa(&Ksb[stg + 4], gk + 16);
        cpa(&Vsb[stg],     gv);
        cpa(&Vsb[stg + 4], gv + 16);
    };

    load(0); CP_COMMIT();
    load(1); CP_COMMIT();
    for (int kt = 0; kt < NT; kt++) {
        const unsigned* Kh = Ksb + (kt % 3) * ATST;
        const unsigned* Vh = Vsb + (kt % 3) * ATST;
        CP_WAIT(1);
        __syncthreads();                     // tile kt ready; prior compute fenced
        if (kt + 2 < NT) load(kt + 2);       // overwrites stage (kt-1)%3: safe post-sync
        CP_COMMIT();                         // always commit: keeps group count exact

        float sacc[8][4];
        #pragma unroll
        for (int j = 0; j < 8; j++)
            #pragma unroll
            for (int k = 0; k < 4; k++) sacc[j][k] = 0.f;

        #pragma unroll
        for (int kc = 0; kc < 4; kc++) {
            const int lcol = kc*8 + ((lm >> 1) << 2);
            #pragma unroll
            for (int np = 0; np < 4; np++) {
                unsigned t[4];
                ldsm4(t, &Kh[(np*16 + ((lm & 1) << 3) + lr) * 36 + lcol]);
                unsigned b0[2] = { t[0], t[2] };
                unsigned b1[2] = { t[1], t[3] };
                mma16(sacc[np*2],     qf[kc], b0);
                mma16(sacc[np*2 + 1], qf[kc], b1);
            }
        }

        float mx0 = sacc[0][0], mx1 = sacc[0][2];
        #pragma unroll
        for (int nt = 0; nt < 8; nt++) {
            mx0 = fmaxf(mx0, fmaxf(sacc[nt][0], sacc[nt][1]));
            mx1 = fmaxf(mx1, fmaxf(sacc[nt][2], sacc[nt][3]));
        }
        mx0 = fmaxf(mx0, __shfl_xor_sync(0xFFFFFFFFu, mx0, 1));
        mx0 = fmaxf(mx0, __shfl_xor_sync(0xFFFFFFFFu, mx0, 2));
        mx1 = fmaxf(mx1, __shfl_xor_sync(0xFFFFFFFFu, mx1, 1));
        mx1 = fmaxf(mx1, __shfl_xor_sync(0xFFFFFFFFu, mx1, 2));
        const float M0 = fmaxf(m0, mx0), M1 = fmaxf(m1, mx1);
        const float f0 = ex2(m0 - M0), f1 = ex2(m1 - M1);
        m0 = M0; m1 = M1;

        float sum0 = 0.f, sum1 = 0.f;
        #pragma unroll
        for (int nt = 0; nt < 8; nt++) {
            const float p0 = ex2(sacc[nt][0] - M0);
            const float p1 = ex2(sacc[nt][1] - M0);
            const float p2 = ex2(sacc[nt][2] - M1);
            const float p3 = ex2(sacc[nt][3] - M1);
            sacc[nt][0] = p0; sacc[nt][1] = p1; sacc[nt][2] = p2; sacc[nt][3] = p3;
            sum0 += p0 + p1; sum1 += p2 + p3;
        }
        sum0 += __shfl_xor_sync(0xFFFFFFFFu, sum0, 1);
        sum0 += __shfl_xor_sync(0xFFFFFFFFu, sum0, 2);
        sum1 += __shfl_xor_sync(0xFFFFFFFFu, sum1, 1);
        sum1 += __shfl_xor_sync(0xFFFFFFFFu, sum1, 2);
        l0 = l0 * f0 + sum0;
        l1 = l1 * f1 + sum1;

        #pragma unroll
        for (int nt = 0; nt < 8; nt++) {
            oacc[nt][0] *= f0; oacc[nt][1] *= f0;
            oacc[nt][2] *= f1; oacc[nt][3] *= f1;
        }

        unsigned pf[4][4];
        #pragma unroll
        for (int kc = 0; kc < 4; kc++) {
            pf[kc][0] = pk(sacc[2*kc][0],     sacc[2*kc][1]);
            pf[kc][1] = pk(sacc[2*kc][2],     sacc[2*kc][3]);
            pf[kc][2] = pk(sacc[2*kc + 1][0], sacc[2*kc + 1][1]);
            pf[kc][3] = pk(sacc[2*kc + 1][2], sacc[2*kc + 1][3]);
        }

        #pragma unroll
        for (int kc = 0; kc < 4; kc++) {
            const int vrow = kc*16 + ((lm & 1) << 3) + lr;
            #pragma unroll
            for (int np2 = 0; np2 < 4; np2++) {
                const int vcol = np2*8 + ((lm >> 1) << 2);
                unsigned t[4];
                ldsm4t(t, &Vh[vrow * 36 + vcol]);
                unsigned b0[2] = { t[0], t[1] };
                unsigned b1[2] = { t[2], t[3] };
                mma16(oacc[np2*2],     pf[kc], b0);
                mma16(oacc[np2*2 + 1], pf[kc], b1);
            }
        }
    }

    const int b = bh >> 4, h = bh & 15;
    const float inv0 = 1.f / l0, inv1 = 1.f / l1;
    const size_t row0 = (size_t)(b * SS + q0 + mr0 + g)     * (DD/2) + h * (HD/2);
    const size_t row1 = (size_t)(b * SS + q0 + mr0 + g + 8) * (DD/2) + h * (HD/2);
    #pragma unroll
    for (int nt = 0; nt < 8; nt++) {
        g_ctx[row0 + nt*4 + tg] = pk(oacc[nt][0] * inv0, oacc[nt][1] * inv0);
        g_ctx[row1 + nt*4 + tg] = pk(oacc[nt][2] * inv1, oacc[nt][3] * inv1);
    }
}

// ---------------- launch ----------------
extern "C" void kernel_launch(void* const* d_in, const int* in_sizes, int n_in,
                              void* d_out, int out_size)
{
    const float* x      = (const float*)d_in[0];
    const float* gamma  = (const float*)d_in[1];
    const float* beta   = (const float*)d_in[2];
    const float* w_qkv  = (const float*)d_in[3];
    const float* b_qkv  = (const float*)d_in[4];
    const float* w_out  = (const float*)d_in[5];
    const float* b_out  = (const float*)d_in[6];
    const float* w_gate = (const float*)d_in[7];
    const float* b_gate = (const float*)d_in[8];
    float* out = (float*)d_out;

    void *p_xn, *p_ctx, *p_gt, *p_wx, *p_wo;
    cudaGetSymbolAddress(&p_xn,  g_xn);
    cudaGetSymbolAddress(&p_ctx, g_ctx);
    cudaGetSymbolAddress(&p_gt,  g_gt);
    cudaGetSymbolAddress(&p_wx,  g_wxT);
    cudaGetSymbolAddress(&p_wo,  g_woT);

    cudaFuncSetAttribute(gemm_bf16,
                         cudaFuncAttributeMaxDynamicSharedMemorySize,
                         GEMM_SMEM_BYTES);
    cudaFuncSetAttribute(attn_kernel,
                         cudaFuncAttributeMaxDynamicSharedMemorySize,
                         ATT_SMEM_BYTES);

    // fused LN + weight transposes: one launch
    prologue<<<MROWS + 4096 + 1024, 256>>>(x, gamma, beta, w_qkv, w_gate, w_out);

    // merged QKV+gate: [4096,1024] x [4096,1024]^T
    gemm_bf16<<<dim3(32, 32), 256, GEMM_SMEM_BYTES>>>(
        (const __nv_bfloat16*)p_xn, (const __nv_bfloat16*)p_wx,
        b_qkv, b_gate, (float*)p_gt, nullptr, nullptr, DD, 1);

    attn_kernel<<<dim3(SS / 128, BB * HH), 256, ATT_SMEM_BYTES>>>();

    // out proj fused: (ctx@w_out + b_out) * sigmoid(g_gt) + x -> d_out
    gemm_bf16<<<dim3(8, 32), 256, GEMM_SMEM_BYTES>>>(
        (const __nv_bfloat16*)p_ctx, (const __nv_bfloat16*)p_wo,
        b_out, nullptr, out, (const float*)p_gt, x, DD, 3);
}

// round 14
// speedup vs baseline: 1.0549x; 1.0175x over previous
#include <cuda_runtime.h>
#include <cuda_bf16.h>
#include <math.h>

#define BB 2
#define SS 2048
#define DD 1024
#define HH 16
#define HD 64
#define MROWS (BB*SS)          // 4096
#define QSCALE 0.1803368801111204f   // 0.125 * log2(e)

// ---------------- scratch (device globals; no allocation) ----------------
__device__ __align__(16) unsigned g_xn  [MROWS*DD/2];       // bf16 [M][D]
__device__ __align__(16) unsigned g_q   [BB*HH*SS*HD/2];    // bf16 [B,H,S,HD] (pre-scaled)
__device__ __align__(16) unsigned g_k   [BB*HH*SS*HD/2];
__device__ __align__(16) unsigned g_v   [BB*HH*SS*HD/2];
__device__ __align__(16) unsigned g_ctx [MROWS*DD/2];       // bf16 [B,S,D]
__device__ __align__(16) float    g_gt  [MROWS*DD];         // f32 gate pre-activation
__device__ __align__(16) unsigned g_wxT [4*DD*DD/2];        // bf16 [wq;wk;wv;wg]^T [4096][1024]
__device__ __align__(16) unsigned g_woT [DD*DD/2];          // bf16 [D][D]

// ---------------- helpers ----------------
__device__ __forceinline__ float ex2(float x) {
    float y; asm("ex2.approx.ftz.f32 %0, %1;" : "=f"(y) : "f"(x)); return y;
}
__device__ __forceinline__ unsigned pk(float lo, float hi) {
    unsigned r; asm("cvt.rn.bf16x2.f32 %0, %1, %2;" : "=r"(r) : "f"(hi), "f"(lo));
    return r;
}
__device__ __forceinline__ void mma16(float* d, const unsigned* a, const unsigned* b) {
    asm volatile(
        "mma.sync.aligned.m16n8k16.row.col.f32.bf16.bf16.f32 "
        "{%0,%1,%2,%3}, {%4,%5,%6,%7}, {%8,%9}, {%0,%1,%2,%3};"
        : "+f"(d[0]), "+f"(d[1]), "+f"(d[2]), "+f"(d[3])
        : "r"(a[0]), "r"(a[1]), "r"(a[2]), "r"(a[3]),
          "r"(b[0]), "r"(b[1]));
}
__device__ __forceinline__ void ldsm4(unsigned* r, const unsigned* p) {
    unsigned addr = (unsigned)__cvta_generic_to_shared(p);
    asm volatile("ldmatrix.sync.aligned.m8n8.x4.shared.b16 {%0,%1,%2,%3}, [%4];"
                 : "=r"(r[0]), "=r"(r[1]), "=r"(r[2]), "=r"(r[3]) : "r"(addr));
}
__device__ __forceinline__ void ldsm4t(unsigned* r, const unsigned* p) {
    unsigned addr = (unsigned)__cvta_generic_to_shared(p);
    asm volatile("ldmatrix.sync.aligned.m8n8.x4.trans.shared.b16 {%0,%1,%2,%3}, [%4];"
                 : "=r"(r[0]), "=r"(r[1]), "=r"(r[2]), "=r"(r[3]) : "r"(addr));
}
__device__ __forceinline__ void cpa(void* s, const void* g) {
    unsigned sa = (unsigned)__cvta_generic_to_shared(s);
    asm volatile("cp.async.cg.shared.global [%0], [%1], 16;" :: "r"(sa), "l"(g));
}
#define CP_COMMIT() asm volatile("cp.async.commit_group;" ::: "memory")
#define CP_WAIT(n)  asm volatile("cp.async.wait_group %0;" :: "n"(n) : "memory")

// ---------------- fused prologue: LayerNorm + all weight transposes ----------
__global__ __launch_bounds__(256) void prologue(
    const float* __restrict__ x, const float* __restrict__ gamma,
    const float* __restrict__ beta,
    const float* __restrict__ w_qkv, const float* __restrict__ w_gate,
    const float* __restrict__ w_out)
{
    int blk = blockIdx.x;
    const int tid = threadIdx.x;

    if (blk < MROWS) {
        const int row = blk;
        const float4 v = reinterpret_cast<const float4*>(x + (size_t)row * DD)[tid];
        float s  = v.x + v.y + v.z + v.w;
        float s2 = v.x*v.x + v.y*v.y + v.z*v.z + v.w*v.w;
        #pragma unroll
        for (int o = 16; o > 0; o >>= 1) {
            s  += __shfl_xor_sync(0xFFFFFFFFu, s,  o);
            s2 += __shfl_xor_sync(0xFFFFFFFFu, s2, o);
        }
        __shared__ float ws[8], ws2[8];
        if ((tid & 31) == 0) { ws[tid >> 5] = s; ws2[tid >> 5] = s2; }
        __syncthreads();
        float st = 0.f, st2 = 0.f;
        #pragma unroll
        for (int i = 0; i < 8; i++) { st += ws[i]; st2 += ws2[i]; }
        const float mu  = st * (1.f / DD);
        const float var = st2 * (1.f / DD) - mu * mu;
        const float inv = rsqrtf(var + 1e-5f);
        const float4 gm = reinterpret_cast<const float4*>(gamma)[tid];
        const float4 bt = reinterpret_cast<const float4*>(beta)[tid];
        uint2 o;
        o.x = pk((v.x - mu) * inv * gm.x + bt.x, (v.y - mu) * inv * gm.y + bt.y);
        o.y = pk((v.z - mu) * inv * gm.z + bt.z, (v.w - mu) * inv * gm.w + bt.w);
        reinterpret_cast<uint2*>(g_xn)[row * 256 + tid] = o;
        return;
    }

    blk -= MROWS;
    __shared__ float s[32][33];
    const int tx = tid & 31, ty = tid >> 5;
    const float* src; unsigned* dstw; int N, rowoff, bx, by;
    if (blk < 4096) {
        bx = blk & 127; by = blk >> 7;
        if (bx < 96) { src = w_qkv;  N = 3 * DD; rowoff = 0; }
        else         { src = w_gate; N = DD; bx -= 96; rowoff = 3 * DD; }
        dstw = g_wxT;
    } else {
        blk -= 4096;
        bx = blk & 31; by = blk >> 5;
        src = w_out; N = DD; rowoff = 0; dstw = g_woT;
    }
    __nv_bfloat16* dst = reinterpret_cast<__nv_bfloat16*>(dstw);
    const int n0 = bx << 5, k0 = by << 5;
    #pragma unroll
    for (int i = 0; i < 4; i++)
        s[ty + 8*i][tx] = src[(size_t)(k0 + ty + 8*i) * N + n0 + tx];
    __syncthreads();
    #pragma unroll
    for (int i = 0; i < 4; i++)
        dst[(size_t)(rowoff + n0 + ty + 8*i) * DD + k0 + tx] = __float2bfloat16(s[tx][ty + 8*i]);
}

// ---------------- shared GEMM machinery (8 warps, 128x128, 5-stage) ----------
#define NSTG 5
#define GS 2560                     // words per stage per operand: 128*20
#define GEMM_SMEM_BYTES (2 * NSTG * GS * 4)   // 102400

#define GEMM_PREAMBLE                                                          \
    extern __shared__ unsigned gsm[];                                          \
    unsigned* As = gsm;                                                        \
    unsigned* Bs = gsm + NSTG * GS;                                            \
    const int tid  = threadIdx.x;                                              \
    const int warp = tid >> 5, lane = tid & 31;                                \
    const int wm = warp >> 1, wn = warp & 1;                                   \
    const int g  = lane >> 2, tg = lane & 3;                                   \
    const int lm = lane >> 3, lr = lane & 7;                                   \
    const int brow = blockIdx.y << 7, bcol = blockIdx.x << 7;                  \
    float acc[2][8][4];                                                        \
    _Pragma("unroll")                                                          \
    for (int i = 0; i < 2; i++)                                                \
        _Pragma("unroll")                                                      \
        for (int j = 0; j < 8; j++)                                            \
            _Pragma("unroll")                                                  \
            for (int k = 0; k < 4; k++) acc[i][j][k] = 0.f;                    \
    const int arow = tid >> 1;                                                 \
    const int akp  = (tid & 1) << 3;                                           \
    auto issue = [&](int kt) {                                                 \
        const int st = (kt % NSTG) * GS + arow * 20 + akp;                     \
        const char* ga = (const char*)(A  + (size_t)(brow + arow) * K + kt * 32 + akp * 2); \
        const char* gb = (const char*)(BT + (size_t)(bcol + arow) * K + kt * 32 + akp * 2); \
        cpa(&As[st],     ga);                                                  \
        cpa(&As[st + 4], ga + 16);                                             \
        cpa(&Bs[st],     gb);                                                  \
        cpa(&Bs[st + 4], gb + 16);                                             \
    };                                                                         \
    auto compute = [&](int buf) {                                              \
        const unsigned* Ab = As + buf * GS;                                    \
        const unsigned* Bb = Bs + buf * GS;                                    \
        _Pragma("unroll")                                                      \
        for (int step = 0; step < 2; step++) {                                 \
            const int lcol = (step << 3) + ((lm >> 1) << 2);                   \
            unsigned af[2][4];                                                 \
            _Pragma("unroll")                                                  \
            for (int mt = 0; mt < 2; mt++) {                                   \
                const int row = (wm << 5) + (mt << 4) + ((lm & 1) << 3) + lr;  \
                ldsm4(af[mt], &Ab[row * 20 + lcol]);                           \
            }                                                                  \
            unsigned bfg[8][2];                                                \
            _Pragma("unroll")                                                  \
            for (int np = 0; np < 4; np++) {                                   \
                const int row = (wn << 6) + (np << 4) + ((lm & 1) << 3) + lr;  \
                unsigned t[4];                                                 \
                ldsm4(t, &Bb[row * 20 + lcol]);                                \
                bfg[np*2][0]   = t[0]; bfg[np*2+1][0] = t[1];                  \
                bfg[np*2][1]   = t[2]; bfg[np*2+1][1] = t[3];                  \
            }                                                                  \
            _Pragma("unroll")                                                  \
            for (int mt = 0; mt < 2; mt++)                                     \
                _Pragma("unroll")                                              \
                for (int nt = 0; nt < 8; nt++)                                 \
                    mma16(acc[mt][nt], af[mt], bfg[nt]);                       \
        }                                                                      \
    };                                                                         \
    const int nk = K >> 5;                                                     \
    issue(0); CP_COMMIT();                                                     \
    issue(1); CP_COMMIT();                                                     \
    issue(2); CP_COMMIT();                                                     \
    issue(3); CP_COMMIT();                                                     \
    for (int kt = 0; kt < nk; kt++) {                                          \
        CP_WAIT(3);                                                            \
        __syncthreads();                                                       \
        if (kt + 4 < nk) issue(kt + 4);                                        \
        CP_COMMIT();                                                           \
        compute(kt % NSTG);                                                    \
    }

// ---- kernel 1: merged QKV+gate (cols <3072 scatter q/k/v; >=3072 g_gt f32) ----
__global__ __launch_bounds__(256, 2) void gemm_qkvg(
    const __nv_bfloat16* __restrict__ A, const __nv_bfloat16* __restrict__ BT,
    const float* __restrict__ bias, const float* __restrict__ bias2,
    float* __restrict__ C, int K)
{
    GEMM_PREAMBLE
    #pragma unroll
    for (int mt = 0; mt < 2; mt++) {
        #pragma unroll
        for (int nt = 0; nt < 8; nt++) {
            const int r0 = brow + (wm << 5) + (mt << 4) + g;
            const int c0 = bcol + (wn << 6) + (nt << 3) + (tg << 1);
            float b0, b1;
            if (c0 >= 3 * DD) { b0 = bias2[c0 - 3 * DD]; b1 = bias2[c0 - 3 * DD + 1]; }
            else              { b0 = bias[c0];           b1 = bias[c0 + 1]; }
            float v00 = acc[mt][nt][0] + b0, v01 = acc[mt][nt][1] + b1;
            float v10 = acc[mt][nt][2] + b0, v11 = acc[mt][nt][3] + b1;
            if (c0 < 3 * DD) {
                const int which = c0 >> 10;
                const int h = (c0 >> 6) & 15;
                const int d = c0 & 63;
                unsigned* dst = (which == 0) ? g_q : (which == 1) ? g_k : g_v;
                if (which == 0) { v00 *= QSCALE; v01 *= QSCALE; v10 *= QSCALE; v11 *= QSCALE; }
                #pragma unroll
                for (int rr = 0; rr < 2; rr++) {
                    const int r = r0 + rr * 8;
                    const int b = r >> 11, s = r & 2047;
                    const size_t idx = (((size_t)((b * HH + h) * SS + s)) * HD + d) >> 1;
                    dst[idx] = rr ? pk(v10, v11) : pk(v00, v01);
                }
            } else {
                const int cg = c0 - 3 * DD;
                *reinterpret_cast<float2*>(&C[(size_t)r0 * DD + cg])       = make_float2(v00, v01);
                *reinterpret_cast<float2*>(&C[(size_t)(r0 + 8) * DD + cg]) = make_float2(v10, v11);
            }
        }
    }
}

// ---- kernel 2: out proj, fused (acc+bias)*sigmoid(g) + x, batched epilogue ----
__global__ __launch_bounds__(256, 2) void gemm_out(
    const __nv_bfloat16* __restrict__ A, const __nv_bfloat16* __restrict__ BT,
    const float* __restrict__ bias, float* __restrict__ C,
    const float* __restrict__ fuse_g, const float* __restrict__ fuse_x, int K)
{
    GEMM_PREAMBLE
    #pragma unroll
    for (int mt = 0; mt < 2; mt++) {
        const int r0 = brow + (wm << 5) + (mt << 4) + g;
        #pragma unroll
        for (int half = 0; half < 2; half++) {
            // batch of 4 fragments: issue all 16 float2 loads first (MLP), then math
            float2 gv0[4], gv1[4], xv0[4], xv1[4];
            size_t off0[4], off1[4];
            #pragma unroll
            for (int j = 0; j < 4; j++) {
                const int nt = half * 4 + j;
                const int c0 = bcol + (wn << 6) + (nt << 3) + (tg << 1);
                off0[j] = (size_t)r0 * DD + c0;
                off1[j] = (size_t)(r0 + 8) * DD + c0;
                gv0[j] = *reinterpret_cast<const float2*>(&fuse_g[off0[j]]);
                gv1[j] = *reinterpret_cast<const float2*>(&fuse_g[off1[j]]);
                xv0[j] = *reinterpret_cast<const float2*>(&fuse_x[off0[j]]);
                xv1[j] = *reinterpret_cast<const float2*>(&fuse_x[off1[j]]);
            }
            #pragma unroll
            for (int j = 0; j < 4; j++) {
                const int nt = half * 4 + j;
                const int c0 = bcol + (wn << 6) + (nt << 3) + (tg << 1);
                const float b0 = bias[c0], b1 = bias[c0 + 1];
                float2 res0, res1;
                res0.x = (acc[mt][nt][0] + b0) / (1.f + ex2(-gv0[j].x * 1.44269504f)) + xv0[j].x;
                res0.y = (acc[mt][nt][1] + b1) / (1.f + ex2(-gv0[j].y * 1.44269504f)) + xv0[j].y;
                res1.x = (acc[mt][nt][2] + b0) / (1.f + ex2(-gv1[j].x * 1.44269504f)) + xv1[j].x;
                res1.y = (acc[mt][nt][3] + b1) / (1.f + ex2(-gv1[j].y * 1.44269504f)) + xv1[j].y;
                *reinterpret_cast<float2*>(&C[off0[j]]) = res0;
                *reinterpret_cast<float2*>(&C[off1[j]]) = res1;
            }
        }
    }
}

// ---------------- flash attention: 3-stage 64-key K/V ring, base-2 softmax ------
#define NT (SS / 64)
#define ATST (64 * 36)
#define ATT_SMEM_BYTES (6 * ATST * 4)        // 55296 B

__global__ __launch_bounds__(256) void attn_kernel()
{
    extern __shared__ unsigned asmem[];
    unsigned* Ksb = asmem;
    unsigned* Vsb = asmem + 3 * ATST;

    const int tid  = threadIdx.x;
    const int warp = tid >> 5, lane = tid & 31;
    const int g  = lane >> 2, tg = lane & 3;
    const int lm = lane >> 3, lr = lane & 7;
    const int bh = blockIdx.y;
    const int q0 = blockIdx.x << 7;
    const int mr0 = warp << 4;

    const unsigned* Qg = g_q + (size_t)bh * SS * 32;
    const unsigned* Kg = g_k + (size_t)bh * SS * 32;
    const unsigned* Vg = g_v + (size_t)bh * SS * 32;

    unsigned qf[4][4];
    {
        const unsigned* r0p = Qg + (size_t)(q0 + mr0 + g) * 32;
        const unsigned* r1p = Qg + (size_t)(q0 + mr0 + g + 8) * 32;
        #pragma unroll
        for (int kc = 0; kc < 4; kc++) {
            qf[kc][0] = r0p[kc*8 + tg];
            qf[kc][1] = r1p[kc*8 + tg];
            qf[kc][2] = r0p[kc*8 + tg + 4];
            qf[kc][3] = r1p[kc*8 + tg + 4];
        }
    }

    float m0 = -1e30f, m1 = -1e30f, l0 = 0.f, l1 = 0.f;
    float oacc[8][4];
    #pragma unroll
    for (int j = 0; j < 8; j++)
        #pragma unroll
        for (int k = 0; k < 4; k++) oacc[j][k] = 0.f;

    const int ld_row = tid >> 2, ld_wo = (tid & 3) << 3;

    auto load = [&](int kt) {
        const int stg = (kt % 3) * ATST + ld_row * 36 + ld_wo;
        const char* gk = (const char*)(Kg + (size_t)(kt * 64 + ld_row) * 32 + ld_wo);
        const char* gv = (const char*)(Vg + (size_t)(kt * 64 + ld_row) * 32 + ld_wo);
        cpa(&Ksb[stg],     gk);
        cpa(&Ksb[stg + 4], gk + 16);
        cpa(&Vsb[stg],     gv);
        cpa(&Vsb[stg + 4], gv + 16);
    };

    load(0); CP_COMMIT();
    load(1); CP_COMMIT();
    for (int kt = 0; kt < NT; kt++) {
        const unsigned* Kh = Ksb + (kt % 3) * ATST;
        const unsigned* Vh = Vsb + (kt % 3) * ATST;
        CP_WAIT(1);
        __syncthreads();
        if (kt + 2 < NT) load(kt + 2);
        CP_COMMIT();

        float sacc[8][4];
        #pragma unroll
        for (int j = 0; j < 8; j++)
            #pragma unroll
            for (int k = 0; k < 4; k++) sacc[j][k] = 0.f;

        #pragma unroll
        for (int kc = 0; kc < 4; kc++) {
            const int lcol = kc*8 + ((lm >> 1) << 2);
            #pragma unroll
            for (int np = 0; np < 4; np++) {
                unsigned t[4];
                ldsm4(t, &Kh[(np*16 + ((lm & 1) << 3) + lr) * 36 + lcol]);
                unsigned b0[2] = { t[0], t[2] };
                unsigned b1[2] = { t[1], t[3] };
                mma16(sacc[np*2],     qf[kc], b0);
                mma16(sacc[np*2 + 1], qf[kc], b1);
            }
        }

        float mx0 = sacc[0][0], mx1 = sacc[0][2];
        #pragma unroll
        for (int nt = 0; nt < 8; nt++) {
            mx0 = fmaxf(mx0, fmaxf(sacc[nt][0], sacc[nt][1]));
            mx1 = fmaxf(mx1, fmaxf(sacc[nt][2], sacc[nt][3]));
        }
        mx0 = fmaxf(mx0, __shfl_xor_sync(0xFFFFFFFFu, mx0, 1));
        mx0 = fmaxf(mx0, __shfl_xor_sync(0xFFFFFFFFu, mx0, 2));
        mx1 = fmaxf(mx1, __shfl_xor_sync(0xFFFFFFFFu, mx1, 1));
        mx1 = fmaxf(mx1, __shfl_xor_sync(0xFFFFFFFFu, mx1, 2));
        const float M0 = fmaxf(m0, mx0), M1 = fmaxf(m1, mx1);
        const float f0 = ex2(m0 - M0), f1 = ex2(m1 - M1);
        m0 = M0; m1 = M1;

        float sum0 = 0.f, sum1 = 0.f;
        #pragma unroll
        for (int nt = 0; nt < 8; nt++) {
            const float p0 = ex2(sacc[nt][0] - M0);
            const float p1 = ex2(sacc[nt][1] - M0);
            const float p2 = ex2(sacc[nt][2] - M1);
            const float p3 = ex2(sacc[nt][3] - M1);
            sacc[nt][0] = p0; sacc[nt][1] = p1; sacc[nt][2] = p2; sacc[nt][3] = p3;
            sum0 += p0 + p1; sum1 += p2 + p3;
        }
        sum0 += __shfl_xor_sync(0xFFFFFFFFu, sum0, 1);
        sum0 += __shfl_xor_sync(0xFFFFFFFFu, sum0, 2);
        sum1 += __shfl_xor_sync(0xFFFFFFFFu, sum1, 1);
        sum1 += __shfl_xor_sync(0xFFFFFFFFu, sum1, 2);
        l0 = l0 * f0 + sum0;
        l1 = l1 * f1 + sum1;

        #pragma unroll
        for (int nt = 0; nt < 8; nt++) {
            oacc[nt][0] *= f0; oacc[nt][1] *= f0;
            oacc[nt][2] *= f1; oacc[nt][3] *= f1;
        }

        unsigned pf[4][4];
        #pragma unroll
        for (int kc = 0; kc < 4; kc++) {
            pf[kc][0] = pk(sacc[2*kc][0],     sacc[2*kc][1]);
            pf[kc][1] = pk(sacc[2*kc][2],     sacc[2*kc][3]);
            pf[kc][2] = pk(sacc[2*kc + 1][0], sacc[2*kc + 1][1]);
            pf[kc][3] = pk(sacc[2*kc + 1][2], sacc[2*kc + 1][3]);
        }

        #pragma unroll
        for (int kc = 0; kc < 4; kc++) {
            const int vrow = kc*16 + ((lm & 1) << 3) + lr;
            #pragma unroll
            for (int np2 = 0; np2 < 4; np2++) {
                const int vcol = np2*8 + ((lm >> 1) << 2);
                unsigned t[4];
                ldsm4t(t, &Vh[vrow * 36 + vcol]);
                unsigned b0[2] = { t[0], t[1] };
                unsigned b1[2] = { t[2], t[3] };
                mma16(oacc[np2*2],     pf[kc], b0);
                mma16(oacc[np2*2 + 1], pf[kc], b1);
            }
        }
    }

    const int b = bh >> 4, h = bh & 15;
    const float inv0 = 1.f / l0, inv1 = 1.f / l1;
    const size_t row0 = (size_t)(b * SS + q0 + mr0 + g)     * (DD/2) + h * (HD/2);
    const size_t row1 = (size_t)(b * SS + q0 + mr0 + g + 8) * (DD/2) + h * (HD/2);
    #pragma unroll
    for (int nt = 0; nt < 8; nt++) {
        g_ctx[row0 + nt*4 + tg] = pk(oacc[nt][0] * inv0, oacc[nt][1] * inv0);
        g_ctx[row1 + nt*4 + tg] = pk(oacc[nt][2] * inv1, oacc[nt][3] * inv1);
    }
}

// ---------------- launch ----------------
extern "C" void kernel_launch(void* const* d_in, const int* in_sizes, int n_in,
                              void* d_out, int out_size)
{
    const float* x      = (const float*)d_in[0];
    const float* gamma  = (const float*)d_in[1];
    const float* beta   = (const float*)d_in[2];
    const float* w_qkv  = (const float*)d_in[3];
    const float* b_qkv  = (const float*)d_in[4];
    const float* w_out  = (const float*)d_in[5];
    const float* b_out  = (const float*)d_in[6];
    const float* w_gate = (const float*)d_in[7];
    const float* b_gate = (const float*)d_in[8];
    float* out = (float*)d_out;

    void *p_xn, *p_ctx, *p_gt, *p_wx, *p_wo;
    cudaGetSymbolAddress(&p_xn,  g_xn);
    cudaGetSymbolAddress(&p_ctx, g_ctx);
    cudaGetSymbolAddress(&p_gt,  g_gt);
    cudaGetSymbolAddress(&p_wx,  g_wxT);
    cudaGetSymbolAddress(&p_wo,  g_woT);

    cudaFuncSetAttribute(gemm_qkvg,
                         cudaFuncAttributeMaxDynamicSharedMemorySize, GEMM_SMEM_BYTES);
    cudaFuncSetAttribute(gemm_out,
                         cudaFuncAttributeMaxDynamicSharedMemorySize, GEMM_SMEM_BYTES);
    cudaFuncSetAttribute(attn_kernel,
                         cudaFuncAttributeMaxDynamicSharedMemorySize, ATT_SMEM_BYTES);

    prologue<<<MROWS + 4096 + 1024, 256>>>(x, gamma, beta, w_qkv, w_gate, w_out);

    gemm_qkvg<<<dim3(32, 32), 256, GEMM_SMEM_BYTES>>>(
        (const __nv_bfloat16*)p_xn, (const __nv_bfloat16*)p_wx,
        b_qkv, b_gate, (float*)p_gt, DD);

    attn_kernel<<<dim3(SS / 128, BB * HH), 256, ATT_SMEM_BYTES>>>();

    gemm_out<<<dim3(8, 32), 256, GEMM_SMEM_BYTES>>>(
        (const __nv_bfloat16*)p_ctx, (const __nv_bfloat16*)p_wo,
        b_out, out, (const float*)p_gt, x, DD);
}

// round 15
// speedup vs baseline: 1.0556x; 1.0007x over previous
#include <cuda_runtime.h>
#include <cuda_bf16.h>
#include <math.h>

#define BB 2
#define SS 2048
#define DD 1024
#define HH 16
#define HD 64
#define MROWS (BB*SS)          // 4096
#define QSCALE 0.1803368801111204f   // 0.125 * log2(e)

// ---------------- scratch (device globals; no allocation) ----------------
__device__ __align__(16) unsigned g_xn  [MROWS*DD/2];       // bf16 [M][D]
__device__ __align__(16) unsigned g_q   [BB*HH*SS*HD/2];    // bf16 [B,H,S,HD] (pre-scaled)
__device__ __align__(16) unsigned g_k   [BB*HH*SS*HD/2];
__device__ __align__(16) unsigned g_v   [BB*HH*SS*HD/2];
__device__ __align__(16) unsigned g_ctx [MROWS*DD/2];       // bf16 [B,S,D]
__device__ __align__(16) float    g_gt  [MROWS*DD];         // f32 gate pre-activation
__device__ __align__(16) unsigned g_wxT [4*DD*DD/2];        // bf16 [wq;wk;wv;wg]^T [4096][1024]
__device__ __align__(16) unsigned g_woT [DD*DD/2];          // bf16 [D][D]

// ---------------- helpers ----------------
__device__ __forceinline__ float ex2(float x) {
    float y; asm("ex2.approx.ftz.f32 %0, %1;" : "=f"(y) : "f"(x)); return y;
}
__device__ __forceinline__ unsigned pk(float lo, float hi) {
    unsigned r; asm("cvt.rn.bf16x2.f32 %0, %1, %2;" : "=r"(r) : "f"(hi), "f"(lo));
    return r;
}
__device__ __forceinline__ void mma16(float* d, const unsigned* a, const unsigned* b) {
    asm volatile(
        "mma.sync.aligned.m16n8k16.row.col.f32.bf16.bf16.f32 "
        "{%0,%1,%2,%3}, {%4,%5,%6,%7}, {%8,%9}, {%0,%1,%2,%3};"
        : "+f"(d[0]), "+f"(d[1]), "+f"(d[2]), "+f"(d[3])
        : "r"(a[0]), "r"(a[1]), "r"(a[2]), "r"(a[3]),
          "r"(b[0]), "r"(b[1]));
}
__device__ __forceinline__ void ldsm4(unsigned* r, const unsigned* p) {
    unsigned addr = (unsigned)__cvta_generic_to_shared(p);
    asm volatile("ldmatrix.sync.aligned.m8n8.x4.shared.b16 {%0,%1,%2,%3}, [%4];"
                 : "=r"(r[0]), "=r"(r[1]), "=r"(r[2]), "=r"(r[3]) : "r"(addr));
}
__device__ __forceinline__ void ldsm4t(unsigned* r, const unsigned* p) {
    unsigned addr = (unsigned)__cvta_generic_to_shared(p);
    asm volatile("ldmatrix.sync.aligned.m8n8.x4.trans.shared.b16 {%0,%1,%2,%3}, [%4];"
                 : "=r"(r[0]), "=r"(r[1]), "=r"(r[2]), "=r"(r[3]) : "r"(addr));
}
__device__ __forceinline__ void cpa(void* s, const void* g) {
    unsigned sa = (unsigned)__cvta_generic_to_shared(s);
    asm volatile("cp.async.cg.shared.global [%0], [%1], 16;" :: "r"(sa), "l"(g));
}
__device__ __forceinline__ void pf_l2(const void* p) {
    asm volatile("prefetch.global.L2 [%0];" :: "l"(p));
}
#define CP_COMMIT() asm volatile("cp.async.commit_group;" ::: "memory")
#define CP_WAIT(n)  asm volatile("cp.async.wait_group %0;" :: "n"(n) : "memory")

// ---------------- fused prologue: LayerNorm + all weight transposes ----------
__global__ __launch_bounds__(256) void prologue(
    const float* __restrict__ x, const float* __restrict__ gamma,
    const float* __restrict__ beta,
    const float* __restrict__ w_qkv, const float* __restrict__ w_gate,
    const float* __restrict__ w_out)
{
    int blk = blockIdx.x;
    const int tid = threadIdx.x;

    if (blk < MROWS) {
        const int row = blk;
        const float4 v = reinterpret_cast<const float4*>(x + (size_t)row * DD)[tid];
        float s  = v.x + v.y + v.z + v.w;
        float s2 = v.x*v.x + v.y*v.y + v.z*v.z + v.w*v.w;
        #pragma unroll
        for (int o = 16; o > 0; o >>= 1) {
            s  += __shfl_xor_sync(0xFFFFFFFFu, s,  o);
            s2 += __shfl_xor_sync(0xFFFFFFFFu, s2, o);
        }
        __shared__ float ws[8], ws2[8];
        if ((tid & 31) == 0) { ws[tid >> 5] = s; ws2[tid >> 5] = s2; }
        __syncthreads();
        float st = 0.f, st2 = 0.f;
        #pragma unroll
        for (int i = 0; i < 8; i++) { st += ws[i]; st2 += ws2[i]; }
        const float mu  = st * (1.f / DD);
        const float var = st2 * (1.f / DD) - mu * mu;
        const float inv = rsqrtf(var + 1e-5f);
        const float4 gm = reinterpret_cast<const float4*>(gamma)[tid];
        const float4 bt = reinterpret_cast<const float4*>(beta)[tid];
        uint2 o;
        o.x = pk((v.x - mu) * inv * gm.x + bt.x, (v.y - mu) * inv * gm.y + bt.y);
        o.y = pk((v.z - mu) * inv * gm.z + bt.z, (v.w - mu) * inv * gm.w + bt.w);
        reinterpret_cast<uint2*>(g_xn)[row * 256 + tid] = o;
        return;
    }

    blk -= MROWS;
    __shared__ float s[32][33];
    const int tx = tid & 31, ty = tid >> 5;
    const float* src; unsigned* dstw; int N, rowoff, bx, by;
    if (blk < 4096) {
        bx = blk & 127; by = blk >> 7;
        if (bx < 96) { src = w_qkv;  N = 3 * DD; rowoff = 0; }
        else         { src = w_gate; N = DD; bx -= 96; rowoff = 3 * DD; }
        dstw = g_wxT;
    } else {
        blk -= 4096;
        bx = blk & 31; by = blk >> 5;
        src = w_out; N = DD; rowoff = 0; dstw = g_woT;
    }
    __nv_bfloat16* dst = reinterpret_cast<__nv_bfloat16*>(dstw);
    const int n0 = bx << 5, k0 = by << 5;
    #pragma unroll
    for (int i = 0; i < 4; i++)
        s[ty + 8*i][tx] = src[(size_t)(k0 + ty + 8*i) * N + n0 + tx];
    __syncthreads();
    #pragma unroll
    for (int i = 0; i < 4; i++)
        dst[(size_t)(rowoff + n0 + ty + 8*i) * DD + k0 + tx] = __float2bfloat16(s[tx][ty + 8*i]);
}

// ---------------- shared GEMM machinery (8 warps, 128x128, 5-stage) ----------
#define NSTG 5
#define GS 2560                     // words per stage per operand: 128*20
#define GEMM_SMEM_BYTES (2 * NSTG * GS * 4)   // 102400

#define GEMM_PREAMBLE                                                          \
    extern __shared__ unsigned gsm[];                                          \
    unsigned* As = gsm;                                                        \
    unsigned* Bs = gsm + NSTG * GS;                                            \
    const int tid  = threadIdx.x;                                              \
    const int warp = tid >> 5, lane = tid & 31;                                \
    const int wm = warp >> 1, wn = warp & 1;                                   \
    const int g  = lane >> 2, tg = lane & 3;                                   \
    const int lm = lane >> 3, lr = lane & 7;                                   \
    const int brow = blockIdx.y << 7, bcol = blockIdx.x << 7;                  \
    float acc[2][8][4];                                                        \
    _Pragma("unroll")                                                          \
    for (int i = 0; i < 2; i++)                                                \
        _Pragma("unroll")                                                      \
        for (int j = 0; j < 8; j++)                                            \
            _Pragma("unroll")                                                  \
            for (int k = 0; k < 4; k++) acc[i][j][k] = 0.f;                    \
    const int arow = tid >> 1;                                                 \
    const int akp  = (tid & 1) << 3;                                           \
    auto issue = [&](int kt) {                                                 \
        const int st = (kt % NSTG) * GS + arow * 20 + akp;                     \
        const char* ga = (const char*)(A  + (size_t)(brow + arow) * K + kt * 32 + akp * 2); \
        const char* gb = (const char*)(BT + (size_t)(bcol + arow) * K + kt * 32 + akp * 2); \
        cpa(&As[st],     ga);                                                  \
        cpa(&As[st + 4], ga + 16);                                             \
        cpa(&Bs[st],     gb);                                                  \
        cpa(&Bs[st + 4], gb + 16);                                             \
    };                                                                         \
    auto compute = [&](int buf) {                                              \
        const unsigned* Ab = As + buf * GS;                                    \
        const unsigned* Bb = Bs + buf * GS;                                    \
        _Pragma("unroll")                                                      \
        for (int step = 0; step < 2; step++) {                                 \
            const int lcol = (step << 3) + ((lm >> 1) << 2);                   \
            unsigned af[2][4];                                                 \
            _Pragma("unroll")                                                  \
            for (int mt = 0; mt < 2; mt++) {                                   \
                const int row = (wm << 5) + (mt << 4) + ((lm & 1) << 3) + lr;  \
                ldsm4(af[mt], &Ab[row * 20 + lcol]);                           \
            }                                                                  \
            unsigned bfg[8][2];                                                \
            _Pragma("unroll")                                                  \
            for (int np = 0; np < 4; np++) {                                   \
                const int row = (wn << 6) + (np << 4) + ((lm & 1) << 3) + lr;  \
                unsigned t[4];                                                 \
                ldsm4(t, &Bb[row * 20 + lcol]);                                \
                bfg[np*2][0]   = t[0]; bfg[np*2+1][0] = t[1];                  \
                bfg[np*2][1]   = t[2]; bfg[np*2+1][1] = t[3];                  \
            }                                                                  \
            _Pragma("unroll")                                                  \
            for (int mt = 0; mt < 2; mt++)                                     \
                _Pragma("unroll")                                              \
                for (int nt = 0; nt < 8; nt++)                                 \
                    mma16(acc[mt][nt], af[mt], bfg[nt]);                       \
        }                                                                      \
    };                                                                         \
    const int nk = K >> 5;                                                     \
    issue(0); CP_COMMIT();                                                     \
    issue(1); CP_COMMIT();                                                     \
    issue(2); CP_COMMIT();                                                     \
    issue(3); CP_COMMIT();                                                     \
    for (int kt = 0; kt < nk; kt++) {                                          \
        CP_WAIT(3);                                                            \
        __syncthreads();                                                       \
        if (kt + 4 < nk) issue(kt + 4);                                        \
        CP_COMMIT();                                                           \
        compute(kt % NSTG);                                                    \
    }

// ---- kernel 1: merged QKV+gate (cols <3072 scatter q/k/v; >=3072 g_gt f32) ----
__global__ __launch_bounds__(256, 2) void gemm_qkvg(
    const __nv_bfloat16* __restrict__ A, const __nv_bfloat16* __restrict__ BT,
    const float* __restrict__ bias, const float* __restrict__ bias2,
    float* __restrict__ C, int K)
{
    GEMM_PREAMBLE
    #pragma unroll
    for (int mt = 0; mt < 2; mt++) {
        #pragma unroll
        for (int nt = 0; nt < 8; nt++) {
            const int r0 = brow + (wm << 5) + (mt << 4) + g;
            const int c0 = bcol + (wn << 6) + (nt << 3) + (tg << 1);
            float b0, b1;
            if (c0 >= 3 * DD) { b0 = bias2[c0 - 3 * DD]; b1 = bias2[c0 - 3 * DD + 1]; }
            else              { b0 = bias[c0];           b1 = bias[c0 + 1]; }
            float v00 = acc[mt][nt][0] + b0, v01 = acc[mt][nt][1] + b1;
            float v10 = acc[mt][nt][2] + b0, v11 = acc[mt][nt][3] + b1;
            if (c0 < 3 * DD) {
                const int which = c0 >> 10;
                const int h = (c0 >> 6) & 15;
                const int d = c0 & 63;
                unsigned* dst = (which == 0) ? g_q : (which == 1) ? g_k : g_v;
                if (which == 0) { v00 *= QSCALE; v01 *= QSCALE; v10 *= QSCALE; v11 *= QSCALE; }
                #pragma unroll
                for (int rr = 0; rr < 2; rr++) {
                    const int r = r0 + rr * 8;
                    const int b = r >> 11, s = r & 2047;
                    const size_t idx = (((size_t)((b * HH + h) * SS + s)) * HD + d) >> 1;
                    dst[idx] = rr ? pk(v10, v11) : pk(v00, v01);
                }
            } else {
                const int cg = c0 - 3 * DD;
                *reinterpret_cast<float2*>(&C[(size_t)r0 * DD + cg])       = make_float2(v00, v01);
                *reinterpret_cast<float2*>(&C[(size_t)(r0 + 8) * DD + cg]) = make_float2(v10, v11);
            }
        }
    }
}

// ---- kernel 2: out proj, fused (acc+bias)*sigmoid(g) + x, batched epilogue,
//      with L2 prefetch of g/x tiles issued before the mainloop ----
__global__ __launch_bounds__(256, 2) void gemm_out(
    const __nv_bfloat16* __restrict__ A, const __nv_bfloat16* __restrict__ BT,
    const float* __restrict__ bias, float* __restrict__ C,
    const float* __restrict__ fuse_g, const float* __restrict__ fuse_x, int K)
{
    // prefetch the epilogue operand tiles into L2 while the mainloop runs.
    // CTA tile: 128 rows x 128 f32 cols = 64KB per operand = 512 x 128B lines.
    // 256 threads x 2 lines x 2 operands covers it exactly.
    {
        const int prow = threadIdx.x >> 1;                    // 0..127
        const int pcol = (threadIdx.x & 1) << 6;              // 0 / 64 floats
        const size_t poff = (size_t)((blockIdx.y << 7) + prow) * DD
                          + (blockIdx.x << 7) + pcol;
        pf_l2(fuse_g + poff);
        pf_l2(fuse_g + poff + 32);
        pf_l2(fuse_x + poff);
        pf_l2(fuse_x + poff + 32);
    }

    GEMM_PREAMBLE
    #pragma unroll
    for (int mt = 0; mt < 2; mt++) {
        const int r0 = brow + (wm << 5) + (mt << 4) + g;
        #pragma unroll
        for (int half = 0; half < 2; half++) {
            // batch of 4 fragments: issue all 16 float2 loads first (MLP), then math
            float2 gv0[4], gv1[4], xv0[4], xv1[4];
            size_t off0[4], off1[4];
            #pragma unroll
            for (int j = 0; j < 4; j++) {
                const int nt = half * 4 + j;
                const int c0 = bcol + (wn << 6) + (nt << 3) + (tg << 1);
                off0[j] = (size_t)r0 * DD + c0;
                off1[j] = (size_t)(r0 + 8) * DD + c0;
                gv0[j] = *reinterpret_cast<const float2*>(&fuse_g[off0[j]]);
                gv1[j] = *reinterpret_cast<const float2*>(&fuse_g[off1[j]]);
                xv0[j] = *reinterpret_cast<const float2*>(&fuse_x[off0[j]]);
                xv1[j] = *reinterpret_cast<const float2*>(&fuse_x[off1[j]]);
            }
            #pragma unroll
            for (int j = 0; j < 4; j++) {
                const int nt = half * 4 + j;
                const int c0 = bcol + (wn << 6) + (nt << 3) + (tg << 1);
                const float b0 = bias[c0], b1 = bias[c0 + 1];
                float2 res0, res1;
                res0.x = (acc[mt][nt][0] + b0) / (1.f + ex2(-gv0[j].x * 1.44269504f)) + xv0[j].x;
                res0.y = (acc[mt][nt][1] + b1) / (1.f + ex2(-gv0[j].y * 1.44269504f)) + xv0[j].y;
                res1.x = (acc[mt][nt][2] + b0) / (1.f + ex2(-gv1[j].x * 1.44269504f)) + xv1[j].x;
                res1.y = (acc[mt][nt][3] + b1) / (1.f + ex2(-gv1[j].y * 1.44269504f)) + xv1[j].y;
                *reinterpret_cast<float2*>(&C[off0[j]]) = res0;
                *reinterpret_cast<float2*>(&C[off1[j]]) = res1;
            }
        }
    }
}

// ---------------- flash attention: 3-stage 64-key K/V ring, base-2 softmax ------
#define NT (SS / 64)
#define ATST (64 * 36)
#define ATT_SMEM_BYTES (6 * ATST * 4)        // 55296 B

__global__ __launch_bounds__(256) void attn_kernel()
{
    extern __shared__ unsigned asmem[];
    unsigned* Ksb = asmem;
    unsigned* Vsb = asmem + 3 * ATST;

    const int tid  = threadIdx.x;
    const int warp = tid >> 5, lane = tid & 31;
    const int g  = lane >> 2, tg = lane & 3;
    const int lm = lane >> 3, lr = lane & 7;
    const int bh = blockIdx.y;
    const int q0 = blockIdx.x << 7;
    const int mr0 = warp << 4;

    const unsigned* Qg = g_q + (size_t)bh * SS * 32;
    const unsigned* Kg = g_k + (size_t)bh * SS * 32;
    const unsigned* Vg = g_v + (size_t)bh * SS * 32;

    unsigned qf[4][4];
    {
        const unsigned* r0p = Qg + (size_t)(q0 + mr0 + g) * 32;
        const unsigned* r1p = Qg + (size_t)(q0 + mr0 + g + 8) * 32;
        #pragma unroll
        for (int kc = 0; kc < 4; kc++) {
            qf[kc][0] = r0p[kc*8 + tg];
            qf[kc][1] = r1p[kc*8 + tg];
            qf[kc][2] = r0p[kc*8 + tg + 4];
            qf[kc][3] = r1p[kc*8 + tg + 4];
        }
    }

    float m0 = -1e30f, m1 = -1e30f, l0 = 0.f, l1 = 0.f;
    float oacc[8][4];
    #pragma unroll
    for (int j = 0; j < 8; j++)
        #pragma unroll
        for (int k = 0; k < 4; k++) oacc[j][k] = 0.f;

    const int ld_row = tid >> 2, ld_wo = (tid & 3) << 3;

    auto load = [&](int kt) {
        const int stg = (kt % 3) * ATST + ld_row * 36 + ld_wo;
        const char* gk = (const char*)(Kg + (size_t)(kt * 64 + ld_row) * 32 + ld_wo);
        const char* gv = (const char*)(Vg + (size_t)(kt * 64 + ld_row) * 32 + ld_wo);
        cpa(&Ksb[stg],     gk);
        cpa(&Ksb[stg + 4], gk + 16);
        cpa(&Vsb[stg],     gv);
        cpa(&Vsb[stg + 4], gv + 16);
    };

    load(0); CP_COMMIT();
    load(1); CP_COMMIT();
    for (int kt = 0; kt < NT; kt++) {
        const unsigned* Kh = Ksb + (kt % 3) * ATST;
        const unsigned* Vh = Vsb + (kt % 3) * ATST;
        CP_WAIT(1);
        __syncthreads();
        if (kt + 2 < NT) load(kt + 2);
        CP_COMMIT();

        float sacc[8][4];
        #pragma unroll
        for (int j = 0; j < 8; j++)
            #pragma unroll
            for (int k = 0; k < 4; k++) sacc[j][k] = 0.f;

        #pragma unroll
        for (int kc = 0; kc < 4; kc++) {
            const int lcol = kc*8 + ((lm >> 1) << 2);
            #pragma unroll
            for (int np = 0; np < 4; np++) {
                unsigned t[4];
                ldsm4(t, &Kh[(np*16 + ((lm & 1) << 3) + lr) * 36 + lcol]);
                unsigned b0[2] = { t[0], t[2] };
                unsigned b1[2] = { t[1], t[3] };
                mma16(sacc[np*2],     qf[kc], b0);
                mma16(sacc[np*2 + 1], qf[kc], b1);
            }
        }

        float mx0 = sacc[0][0], mx1 = sacc[0][2];
        #pragma unroll
        for (int nt = 0; nt < 8; nt++) {
            mx0 = fmaxf(mx0, fmaxf(sacc[nt][0], sacc[nt][1]));
            mx1 = fmaxf(mx1, fmaxf(sacc[nt][2], sacc[nt][3]));
        }
        mx0 = fmaxf(mx0, __shfl_xor_sync(0xFFFFFFFFu, mx0, 1));
        mx0 = fmaxf(mx0, __shfl_xor_sync(0xFFFFFFFFu, mx0, 2));
        mx1 = fmaxf(mx1, __shfl_xor_sync(0xFFFFFFFFu, mx1, 1));
        mx1 = fmaxf(mx1, __shfl_xor_sync(0xFFFFFFFFu, mx1, 2));
        const float M0 = fmaxf(m0, mx0), M1 = fmaxf(m1, mx1);
        const float f0 = ex2(m0 - M0), f1 = ex2(m1 - M1);
        m0 = M0; m1 = M1;

        float sum0 = 0.f, sum1 = 0.f;
        #pragma unroll
        for (int nt = 0; nt < 8; nt++) {
            const float p0 = ex2(sacc[nt][0] - M0);
            const float p1 = ex2(sacc[nt][1] - M0);
            const float p2 = ex2(sacc[nt][2] - M1);
            const float p3 = ex2(sacc[nt][3] - M1);
            sacc[nt][0] = p0; sacc[nt][1] = p1; sacc[nt][2] = p2; sacc[nt][3] = p3;
            sum0 += p0 + p1; sum1 += p2 + p3;
        }
        sum0 += __shfl_xor_sync(0xFFFFFFFFu, sum0, 1);
        sum0 += __shfl_xor_sync(0xFFFFFFFFu, sum0, 2);
        sum1 += __shfl_xor_sync(0xFFFFFFFFu, sum1, 1);
        sum1 += __shfl_xor_sync(0xFFFFFFFFu, sum1, 2);
        l0 = l0 * f0 + sum0;
        l1 = l1 * f1 + sum1;

        #pragma unroll
        for (int nt = 0; nt < 8; nt++) {
            oacc[nt][0] *= f0; oacc[nt][1] *= f0;
            oacc[nt][2] *= f1; oacc[nt][3] *= f1;
        }

        unsigned pf[4][4];
        #pragma unroll
        for (int kc = 0; kc < 4; kc++) {
            pf[kc][0] = pk(sacc[2*kc][0],     sacc[2*kc][1]);
            pf[kc][1] = pk(sacc[2*kc][2],     sacc[2*kc][3]);
            pf[kc][2] = pk(sacc[2*kc + 1][0], sacc[2*kc + 1][1]);
            pf[kc][3] = pk(sacc[2*kc + 1][2], sacc[2*kc + 1][3]);
        }

        #pragma unroll
        for (int kc = 0; kc < 4; kc++) {
            const int vrow = kc*16 + ((lm & 1) << 3) + lr;
            #pragma unroll
            for (int np2 = 0; np2 < 4; np2++) {
                const int vcol = np2*8 + ((lm >> 1) << 2);
                unsigned t[4];
                ldsm4t(t, &Vh[vrow * 36 + vcol]);
                unsigned b0[2] = { t[0], t[1] };
                unsigned b1[2] = { t[2], t[3] };
                mma16(oacc[np2*2],     pf[kc], b0);
                mma16(oacc[np2*2 + 1], pf[kc], b1);
            }
        }
    }

    const int b = bh >> 4, h = bh & 15;
    const float inv0 = 1.f / l0, inv1 = 1.f / l1;
    const size_t row0 = (size_t)(b * SS + q0 + mr0 + g)     * (DD/2) + h * (HD/2);
    const size_t row1 = (size_t)(b * SS + q0 + mr0 + g + 8) * (DD/2) + h * (HD/2);
    #pragma unroll
    for (int nt = 0; nt < 8; nt++) {
        g_ctx[row0 + nt*4 + tg] = pk(oacc[nt][0] * inv0, oacc[nt][1] * inv0);
        g_ctx[row1 + nt*4 + tg] = pk(oacc[nt][2] * inv1, oacc[nt][3] * inv1);
    }
}

// ---------------- launch ----------------
extern "C" void kernel_launch(void* const* d_in, const int* in_sizes, int n_in,
                              void* d_out, int out_size)
{
    const float* x      = (const float*)d_in[0];
    const float* gamma  = (const float*)d_in[1];
    const float* beta   = (const float*)d_in[2];
    const float* w_qkv  = (const float*)d_in[3];
    const float* b_qkv  = (const float*)d_in[4];
    const float* w_out  = (const float*)d_in[5];
    const float* b_out  = (const float*)d_in[6];
    const float* w_gate = (const float*)d_in[7];
    const float* b_gate = (const float*)d_in[8];
    float* out = (float*)d_out;

    void *p_xn, *p_ctx, *p_gt, *p_wx, *p_wo;
    cudaGetSymbolAddress(&p_xn,  g_xn);
    cudaGetSymbolAddress(&p_ctx, g_ctx);
    cudaGetSymbolAddress(&p_gt,  g_gt);
    cudaGetSymbolAddress(&p_wx,  g_wxT);
    cudaGetSymbolAddress(&p_wo,  g_woT);

    cudaFuncSetAttribute(gemm_qkvg,
                         cudaFuncAttributeMaxDynamicSharedMemorySize, GEMM_SMEM_BYTES);
    cudaFuncSetAttribute(gemm_out,
                         cudaFuncAttributeMaxDynamicSharedMemorySize, GEMM_SMEM_BYTES);
    cudaFuncSetAttribute(attn_kernel,
                         cudaFuncAttributeMaxDynamicSharedMemorySize, ATT_SMEM_BYTES);

    prologue<<<MROWS + 4096 + 1024, 256>>>(x, gamma, beta, w_qkv, w_gate, w_out);

    gemm_qkvg<<<dim3(32, 32), 256, GEMM_SMEM_BYTES>>>(
        (const __nv_bfloat16*)p_xn, (const __nv_bfloat16*)p_wx,
        b_qkv, b_gate, (float*)p_gt, DD);

    attn_kernel<<<dim3(SS / 128, BB * HH), 256, ATT_SMEM_BYTES>>>();

    gemm_out<<<dim3(8, 32), 256, GEMM_SMEM_BYTES>>>(
        (const __nv_bfloat16*)p_ctx, (const __nv_bfloat16*)p_wo,
        b_out, out, (const float*)p_gt, x, DD);
}